// round 6
// baseline (speedup 1.0000x reference)
#include <cuda_runtime.h>
#include <math.h>

#define HH 1024
#define WW 1024
#define NIMG 6
#define HW (HH*WW)
#define RPT 16
#define EPSF 1e-3f

// Scratch (device globals: allocation-free rule)
__device__ float g_tmpT[NIMG*HW];   // vertical blur result, TRANSPOSED [img][x][y]
__device__ float g_accT[NIMG*HW];   // sum of log(blur) over sigmas, TRANSPOSED [img][x][y]
__device__ float g_kern[2304];      // 3 gaussian kernels at offsets 0,128,640
__device__ float g_red[4];          // |gx_ref|, |gy_ref|, |gx_ill|, |gy_ill| sums

// ---------------------------------------------------------------------------
// Build the three gaussian kernels (ks = 91, 481, 1501), deterministic tree
// reduction for normalization. Also zeroes the loss accumulators.
// ---------------------------------------------------------------------------
__global__ void init_kernels_k() {
    __shared__ float red[1024];
    const float sig[3] = {15.f, 80.f, 250.f};
    const int   ks [3] = {91, 481, 1501};
    const int   off[3] = {0, 128, 640};
    int tid = threadIdx.x;
    if (tid < 4) g_red[tid] = 0.f;
    for (int s = 0; s < 3; ++s) {
        int n = ks[s];
        float c   = 0.5f * (float)(n - 1);
        float inv = 1.0f / sig[s];
        float local = 0.f;
        for (int t = tid; t < n; t += 1024) {
            float x = ((float)t - c) * inv;
            float v = expf(-0.5f * x * x);
            g_kern[off[s] + t] = v;
            local += v;
        }
        red[tid] = local;
        __syncthreads();
        for (int st = 512; st > 0; st >>= 1) {
            if (tid < st) red[tid] += red[tid + st];
            __syncthreads();
        }
        float s_inv = 1.0f / red[0];
        __syncthreads();   // all reads of red[0] done before next sigma rewrites red
        for (int t = tid; t < n; t += 1024) g_kern[off[s] + t] *= s_inv;
    }
}

// ---------------------------------------------------------------------------
// Separable conv pass. Conv runs along the SLOW dim of the input; lanes run
// along the FAST dim (coalesced). Output-stationary: R=16 accumulators per
// thread + 16-deep circular register window => 1 global load per 16 FMAs.
//
// The tap loop runs over kpad = ceil(ks/16)*16 taps with the kernel
// zero-padded in shared memory: keeps the refill invariant uniform (fixes the
// R1 stale-window remainder bug); padded taps are exact no-ops (k=0).
//
// PASS==1: in = clip(input) [img][y][x], conv over y, out -> g_tmpT[img][x][y]
// PASS==2: in = g_tmpT      [img][x][y], conv over x, out -> g_accT[img][x][y]
//          epilogue: accT (=|first) / (+=) log(max(blur, eps))
// Reflect padding: worst-case source row = o0-p+kpad+15 = 1777 < 2*1023, so a
// single reflection always suffices on both ends.
// ---------------------------------------------------------------------------
template<int PASS>
__global__ void __launch_bounds__(128) conv_k(const float* __restrict__ din,
                                              int koff, int ks, int p, int first)
{
    __shared__ float sk[1504];
    int kpad = (ks + RPT - 1) & ~(RPT - 1);
    int tid = threadIdx.x;
    for (int t = tid; t < kpad; t += 128)
        sk[t] = (t < ks) ? g_kern[koff + t] : 0.f;
    __syncthreads();

    int lane = blockIdx.x * 128 + tid;   // fast dim (x for pass1, y for pass2)
    int o0   = blockIdx.y * RPT;         // slow-dim tile base
    int img  = blockIdx.z;
    const float* __restrict__ base =
        (PASS == 1) ? (din + (size_t)img * HW) : (g_tmpT + (size_t)img * HW);

    float acc[RPT], win[RPT];
#pragma unroll
    for (int r = 0; r < RPT; ++r) acc[r] = 0.f;

    // preload window: rows o0-p .. o0-p+R-1
#pragma unroll
    for (int i = 0; i < RPT; ++i) {
        int s = o0 - p + i;
        s = (s < 0) ? -s : ((s >= HH) ? (2*HH - 2 - s) : s);
        float v = __ldg(base + (size_t)s * WW + lane);
        if (PASS == 1) v = fminf(fmaxf(v, EPSF), 1.0f);
        win[i] = v;
    }

    for (int t = 0; t < kpad; t += RPT) {
#pragma unroll
        for (int j = 0; j < RPT; ++j) {
            float kt = sk[t + j];
#pragma unroll
            for (int r = 0; r < RPT; ++r)
                acc[r] = fmaf(kt, win[(r + j) & (RPT - 1)], acc[r]);
            // refill the slot just fully consumed with row (o0 - p + t + R + j)
            int s = o0 - p + t + RPT + j;
            s = (s < 0) ? -s : ((s >= HH) ? (2*HH - 2 - s) : s);
            float v = __ldg(base + (size_t)s * WW + lane);
            if (PASS == 1) v = fminf(fmaxf(v, EPSF), 1.0f);
            win[j] = v;
        }
    }

    if (PASS == 1) {
        // transposed store: tmpT[img][x=lane][y=o0+r] (16 contiguous floats/thread)
        float* o = g_tmpT + (size_t)img * HW + (size_t)lane * HH + o0;
#pragma unroll
        for (int r = 0; r < RPT; ++r) o[r] = acc[r];
    } else {
        // accT[img][x=o0+r][y=lane] — coalesced across lanes for each r
        float* o = g_accT + (size_t)img * HW + (size_t)o0 * HH + lane;
        if (first) {
#pragma unroll
            for (int r = 0; r < RPT; ++r)
                o[(size_t)r * HH] = logf(fmaxf(acc[r], EPSF));
        } else {
#pragma unroll
            for (int r = 0; r < RPT; ++r)
                o[(size_t)r * HH] += logf(fmaxf(acc[r], EPSF));
        }
    }
}

// ---------------------------------------------------------------------------
// Emit reflectance and illumination (normal NCHW layout) into d_out.
// reflectance = log(clip(in,eps,1)) - acc/3 ; illumination = log(max(in,eps)) - reflectance
// ---------------------------------------------------------------------------
__global__ void fields_k(const float* __restrict__ inp, float* __restrict__ dout) {
    int total = NIMG * HW;
    for (int idx = blockIdx.x * blockDim.x + threadIdx.x; idx < total;
         idx += gridDim.x * blockDim.x) {
        int img = idx >> 20;
        int y   = (idx >> 10) & 1023;
        int x   = idx & 1023;
        float a  = g_accT[((size_t)img << 20) + ((size_t)x << 10) + (size_t)y];
        float ib = a * (1.0f / 3.0f);
        float v  = inp[idx];
        float li = logf(fminf(fmaxf(v, EPSF), 1.0f));
        float refl  = li - ib;
        float illum = logf(fmaxf(v, EPSF)) - refl;
        dout[3 + idx]          = refl;
        dout[3 + total + idx]  = illum;
    }
}

// ---------------------------------------------------------------------------
// Gradient-magnitude sums for both fields (reads d_out, everything L2-hot).
// ---------------------------------------------------------------------------
__global__ void grad_k(const float* __restrict__ dout) {
    const float* __restrict__ refl = dout + 3;
    const float* __restrict__ ill  = dout + 3 + NIMG * HW;
    float s0 = 0.f, s1 = 0.f, s2 = 0.f, s3 = 0.f;
    int total = NIMG * HW;
    for (int idx = blockIdx.x * blockDim.x + threadIdx.x; idx < total;
         idx += gridDim.x * blockDim.x) {
        int x = idx & 1023;
        int y = (idx >> 10) & 1023;
        float r0 = refl[idx], i0 = ill[idx];
        if (x < 1023) {
            s0 += fabsf(r0 - refl[idx + 1]);
            s2 += fabsf(i0 - ill[idx + 1]);
        }
        if (y < 1023) {
            s1 += fabsf(r0 - refl[idx + 1024]);
            s3 += fabsf(i0 - ill[idx + 1024]);
        }
    }
#pragma unroll
    for (int o = 16; o > 0; o >>= 1) {
        s0 += __shfl_down_sync(0xffffffffu, s0, o);
        s1 += __shfl_down_sync(0xffffffffu, s1, o);
        s2 += __shfl_down_sync(0xffffffffu, s2, o);
        s3 += __shfl_down_sync(0xffffffffu, s3, o);
    }
    __shared__ float sb[4][8];
    int wid = threadIdx.x >> 5, lid = threadIdx.x & 31;
    if (lid == 0) { sb[0][wid] = s0; sb[1][wid] = s1; sb[2][wid] = s2; sb[3][wid] = s3; }
    __syncthreads();
    if (threadIdx.x == 0) {
        float t0 = 0.f, t1 = 0.f, t2 = 0.f, t3 = 0.f;
        int nw = blockDim.x >> 5;
        for (int w = 0; w < nw; ++w) {
            t0 += sb[0][w]; t1 += sb[1][w]; t2 += sb[2][w]; t3 += sb[3][w];
        }
        atomicAdd(&g_red[0], t0); atomicAdd(&g_red[1], t1);
        atomicAdd(&g_red[2], t2); atomicAdd(&g_red[3], t3);
    }
}

__global__ void fin_k(float* dout) {
    if (threadIdx.x == 0) {
        float ngx = (float)(NIMG * HH * (WW - 1));
        float ngy = (float)(NIMG * (HH - 1) * WW);
        float ld = g_red[0] / ngx + g_red[1] / ngy;
        float ls = g_red[2] / ngx + g_red[3] / ngy;
        dout[0] = ls;      // DETAIL_WEIGHT = 0, ILLUM_WEIGHT = 1
        dout[1] = ld;
        dout[2] = ls;
    }
}

extern "C" void kernel_launch(void* const* d_in, const int* in_sizes, int n_in,
                              void* d_out, int out_size) {
    const float* inp = (const float*)d_in[0];
    float* out = (float*)d_out;

    init_kernels_k<<<1, 1024>>>();

    const int ks [3] = {91, 481, 1501};
    const int off[3] = {0, 128, 640};
    const int pp [3] = {45, 240, 750};
    dim3 gconv(WW / 128, HH / RPT, NIMG);
    for (int s = 0; s < 3; ++s) {
        conv_k<1><<<gconv, 128>>>(inp, off[s], ks[s], pp[s], 0);
        conv_k<2><<<gconv, 128>>>(inp, off[s], ks[s], pp[s], s == 0);
    }

    fields_k<<<4096, 256>>>(inp, out);
    grad_k<<<2048, 256>>>(out);
    fin_k<<<1, 32>>>(out);
}

// round 7
// speedup vs baseline: 1.1665x; 1.1665x over previous
#include <cuda_runtime.h>
#include <math.h>

#define HH 1024
#define WW 1024
#define NIMG 6
#define HW (HH*WW)
#define RPT 16
#define EPSF 1e-3f

// Scratch (device globals: allocation-free rule)
__device__ float g_tmpT[NIMG*HW];   // vertical blur result, TRANSPOSED [img][x][y]
__device__ float g_acc[NIMG*HW];    // sum of log(blur) over sigmas, NORMAL [img][y][x]
__device__ float g_kern[2304];      // 3 gaussian kernels at offsets 0,128,640
__device__ float g_red[4];          // |gx_ref|, |gy_ref|, |gx_ill|, |gy_ill| sums

// ---- f32x2 packed helpers (FFMA2: ptxas only emits via explicit PTX) ------
__device__ __forceinline__ unsigned long long pk(float a, float b) {
    unsigned long long u;
    asm("mov.b64 %0, {%1, %2};" : "=l"(u) : "f"(a), "f"(b));
    return u;
}
__device__ __forceinline__ float2 unpk(unsigned long long u) {
    float2 v;
    asm("mov.b64 {%0, %1}, %2;" : "=f"(v.x), "=f"(v.y) : "l"(u));
    return v;
}
__device__ __forceinline__ void ffma2(unsigned long long& d,
                                      unsigned long long a, unsigned long long b) {
    asm("fma.rn.f32x2 %0, %1, %2, %0;" : "+l"(d) : "l"(a), "l"(b));
}

// ---------------------------------------------------------------------------
// Build the three gaussian kernels (ks = 91, 481, 1501), deterministic tree
// reduction for normalization. Also zeroes the loss accumulators.
// ---------------------------------------------------------------------------
__global__ void init_kernels_k() {
    __shared__ float red[1024];
    const float sig[3] = {15.f, 80.f, 250.f};
    const int   ks [3] = {91, 481, 1501};
    const int   off[3] = {0, 128, 640};
    int tid = threadIdx.x;
    if (tid < 4) g_red[tid] = 0.f;
    for (int s = 0; s < 3; ++s) {
        int n = ks[s];
        float c   = 0.5f * (float)(n - 1);
        float inv = 1.0f / sig[s];
        float local = 0.f;
        for (int t = tid; t < n; t += 1024) {
            float x = ((float)t - c) * inv;
            float v = expf(-0.5f * x * x);
            g_kern[off[s] + t] = v;
            local += v;
        }
        red[tid] = local;
        __syncthreads();
        for (int st = 512; st > 0; st >>= 1) {
            if (tid < st) red[tid] += red[tid + st];
            __syncthreads();
        }
        float s_inv = 1.0f / red[0];
        __syncthreads();
        for (int t = tid; t < n; t += 1024) g_kern[off[s] + t] *= s_inv;
    }
}

__device__ __forceinline__ int reflect_idx(int s) {
    return (s < 0) ? -s : ((s >= HH) ? (2*HH - 2 - s) : s);
}

// ---------------------------------------------------------------------------
// Separable conv pass, f32x2 packed: each thread owns TWO adjacent fast-dim
// columns. Output-stationary: 16 packed accumulators + 16-deep packed
// circular window => one LDG.64 + one LDS.64 + 16 FFMA2 per tap.
//
// Shared table sk2[t] = { k[t] (0-padded to kpad), byte-offset of refill row
// t+16 (reflect applied, per-block) }. Tap loop runs over kpad taps; padded
// taps multiply by 0 (exact no-op), refills stay in single-reflection range
// (max source row o0-p+kpad+15 = 1777 < 2046 for sigma=250).
//
// PASS==1: in = clip(input) [img][y][x], conv over y, out -> g_tmpT[img][x][y]
// PASS==2: in = g_tmpT      [img][x][y], conv over x, out -> g_acc  [img][y][x]
//          epilogue: acc (=|first) / (+=) log(max(blur, eps))
// ---------------------------------------------------------------------------
template<int PASS>
__global__ void __launch_bounds__(128, 5) conv_k(const float* __restrict__ din,
                                                 int koff, int ks, int p, int first)
{
    __shared__ float2 sk2[1504];
    int kpad = (ks + RPT - 1) & ~(RPT - 1);
    int tid = threadIdx.x;
    int o0  = blockIdx.y * RPT;          // slow-dim tile base
    for (int t = tid; t < kpad; t += 128) {
        float kv = (t < ks) ? g_kern[koff + t] : 0.f;
        int s = reflect_idx(o0 - p + t + RPT);     // refill row for tap t
        sk2[t] = make_float2(kv, __int_as_float(s * (WW * 4)));
    }
    __syncthreads();

    int l   = blockIdx.x * 128 + tid;    // fast-dim pair index (cols 2l, 2l+1)
    int img = blockIdx.z;
    const float* __restrict__ base =
        (PASS == 1) ? (din + (size_t)img * HW) : (g_tmpT + (size_t)img * HW);
    const char* bp = (const char*)base + (size_t)l * 8;   // +8B for the pair

    unsigned long long acc2[RPT], win2[RPT];
#pragma unroll
    for (int r = 0; r < RPT; ++r) acc2[r] = 0ull;

    // preload window: rows o0-p .. o0-p+15
#pragma unroll
    for (int i = 0; i < RPT; ++i) {
        int s = reflect_idx(o0 - p + i);
        float2 v = __ldg((const float2*)(bp + (size_t)s * (WW * 4)));
        if (PASS == 1) {
            v.x = fminf(fmaxf(v.x, EPSF), 1.0f);
            v.y = fminf(fmaxf(v.y, EPSF), 1.0f);
        }
        win2[i] = pk(v.x, v.y);
    }

    for (int t = 0; t < kpad; t += RPT) {
#pragma unroll
        for (int j = 0; j < RPT; ++j) {
            float2 e = sk2[t + j];                 // one LDS.64: (k, offset)
            unsigned long long kk = pk(e.x, e.x);
#pragma unroll
            for (int r = 0; r < RPT; ++r)
                ffma2(acc2[r], kk, win2[(r + j) & (RPT - 1)]);
            float2 v = __ldg((const float2*)(bp + __float_as_int(e.y)));
            if (PASS == 1) {
                v.x = fminf(fmaxf(v.x, EPSF), 1.0f);
                v.y = fminf(fmaxf(v.y, EPSF), 1.0f);
            }
            win2[j] = pk(v.x, v.y);
        }
    }

    if (PASS == 1) {
        // tmpT[img][x][y]: col pair x = 2l, 2l+1; y = o0+r (two 64B runs)
        float* oa = g_tmpT + (size_t)img * HW + (size_t)(2 * l)     * HH + o0;
        float* ob = g_tmpT + (size_t)img * HW + (size_t)(2 * l + 1) * HH + o0;
#pragma unroll
        for (int r = 0; r < RPT; ++r) {
            float2 v = unpk(acc2[r]);
            oa[r] = v.x;
            ob[r] = v.y;
        }
    } else {
        // NORMAL layout: g_acc[img][y][x], y pair = 2l, 2l+1; x = o0+r
        float* oa = g_acc + (size_t)img * HW + (size_t)(2 * l)     * WW + o0;
        float* ob = g_acc + (size_t)img * HW + (size_t)(2 * l + 1) * WW + o0;
        if (first) {
#pragma unroll
            for (int r = 0; r < RPT; ++r) {
                float2 v = unpk(acc2[r]);
                oa[r] = logf(fmaxf(v.x, EPSF));
                ob[r] = logf(fmaxf(v.y, EPSF));
            }
        } else {
#pragma unroll
            for (int r = 0; r < RPT; ++r) {
                float2 v = unpk(acc2[r]);
                oa[r] += logf(fmaxf(v.x, EPSF));
                ob[r] += logf(fmaxf(v.y, EPSF));
            }
        }
    }
}

// ---------------------------------------------------------------------------
// Emit reflectance and illumination (NCHW) into d_out. Fully coalesced now.
// reflectance = log(clip(in,eps,1)) - acc/3 ; illumination = log(max(in,eps)) - refl
// ---------------------------------------------------------------------------
__global__ void fields_k(const float* __restrict__ inp, float* __restrict__ dout) {
    int total = NIMG * HW;
    for (int idx = blockIdx.x * blockDim.x + threadIdx.x; idx < total;
         idx += gridDim.x * blockDim.x) {
        float a  = g_acc[idx];
        float ib = a * (1.0f / 3.0f);
        float v  = inp[idx];
        float li = logf(fminf(fmaxf(v, EPSF), 1.0f));
        float refl  = li - ib;
        float illum = logf(fmaxf(v, EPSF)) - refl;
        dout[3 + idx]          = refl;
        dout[3 + total + idx]  = illum;
    }
}

// ---------------------------------------------------------------------------
// Gradient-magnitude sums for both fields (reads d_out, L2-hot).
// ---------------------------------------------------------------------------
__global__ void grad_k(const float* __restrict__ dout) {
    const float* __restrict__ refl = dout + 3;
    const float* __restrict__ ill  = dout + 3 + NIMG * HW;
    float s0 = 0.f, s1 = 0.f, s2 = 0.f, s3 = 0.f;
    int total = NIMG * HW;
    for (int idx = blockIdx.x * blockDim.x + threadIdx.x; idx < total;
         idx += gridDim.x * blockDim.x) {
        int x = idx & 1023;
        int y = (idx >> 10) & 1023;
        float r0 = refl[idx], i0 = ill[idx];
        if (x < 1023) {
            s0 += fabsf(r0 - refl[idx + 1]);
            s2 += fabsf(i0 - ill[idx + 1]);
        }
        if (y < 1023) {
            s1 += fabsf(r0 - refl[idx + 1024]);
            s3 += fabsf(i0 - ill[idx + 1024]);
        }
    }
#pragma unroll
    for (int o = 16; o > 0; o >>= 1) {
        s0 += __shfl_down_sync(0xffffffffu, s0, o);
        s1 += __shfl_down_sync(0xffffffffu, s1, o);
        s2 += __shfl_down_sync(0xffffffffu, s2, o);
        s3 += __shfl_down_sync(0xffffffffu, s3, o);
    }
    __shared__ float sb[4][8];
    int wid = threadIdx.x >> 5, lid = threadIdx.x & 31;
    if (lid == 0) { sb[0][wid] = s0; sb[1][wid] = s1; sb[2][wid] = s2; sb[3][wid] = s3; }
    __syncthreads();
    if (threadIdx.x == 0) {
        float t0 = 0.f, t1 = 0.f, t2 = 0.f, t3 = 0.f;
        int nw = blockDim.x >> 5;
        for (int w = 0; w < nw; ++w) {
            t0 += sb[0][w]; t1 += sb[1][w]; t2 += sb[2][w]; t3 += sb[3][w];
        }
        atomicAdd(&g_red[0], t0); atomicAdd(&g_red[1], t1);
        atomicAdd(&g_red[2], t2); atomicAdd(&g_red[3], t3);
    }
}

__global__ void fin_k(float* dout) {
    if (threadIdx.x == 0) {
        float ngx = (float)(NIMG * HH * (WW - 1));
        float ngy = (float)(NIMG * (HH - 1) * WW);
        float ld = g_red[0] / ngx + g_red[1] / ngy;
        float ls = g_red[2] / ngx + g_red[3] / ngy;
        dout[0] = ls;      // DETAIL_WEIGHT = 0, ILLUM_WEIGHT = 1
        dout[1] = ld;
        dout[2] = ls;
    }
}

extern "C" void kernel_launch(void* const* d_in, const int* in_sizes, int n_in,
                              void* d_out, int out_size) {
    const float* inp = (const float*)d_in[0];
    float* out = (float*)d_out;

    init_kernels_k<<<1, 1024>>>();

    const int ks [3] = {91, 481, 1501};
    const int off[3] = {0, 128, 640};
    const int pp [3] = {45, 240, 750};
    dim3 gconv(WW / 256, HH / RPT, NIMG);   // 4 x 64 x 6 = 1536 blocks
    for (int s = 0; s < 3; ++s) {
        conv_k<1><<<gconv, 128>>>(inp, off[s], ks[s], pp[s], 0);
        conv_k<2><<<gconv, 128>>>(inp, off[s], ks[s], pp[s], s == 0);
    }

    fields_k<<<4096, 256>>>(inp, out);
    grad_k<<<2048, 256>>>(out);
    fin_k<<<1, 32>>>(out);
}

// round 9
// speedup vs baseline: 1.2274x; 1.0522x over previous
#include <cuda_runtime.h>
#include <math.h>

#define HH 1024
#define WW 1024
#define NIMG 6
#define HW (HH*WW)
#define RPT 16
#define PF 8
#define EPSF 1e-3f

// Scratch (device globals: allocation-free rule)
__device__ float g_tmpT[NIMG*HW];   // vertical blur result, TRANSPOSED [img][x][y]
__device__ float g_acc[NIMG*HW];    // sum of log(blur) over sigmas, NORMAL [img][y][x]
__device__ float g_kern[2304];      // 3 gaussian kernels at offsets 0,128,640
__device__ float g_red[4];          // |gx_ref|, |gy_ref|, |gx_ill|, |gy_ill| sums

// ---- f32x2 packed helpers (FFMA2: ptxas only emits via explicit PTX) ------
__device__ __forceinline__ unsigned long long pk(float a, float b) {
    unsigned long long u;
    asm("mov.b64 %0, {%1, %2};" : "=l"(u) : "f"(a), "f"(b));
    return u;
}
__device__ __forceinline__ float2 unpk(unsigned long long u) {
    float2 v;
    asm("mov.b64 {%0, %1}, %2;" : "=f"(v.x), "=f"(v.y) : "l"(u));
    return v;
}
__device__ __forceinline__ void ffma2(unsigned long long& d,
                                      unsigned long long a, unsigned long long b) {
    asm("fma.rn.f32x2 %0, %1, %2, %0;" : "+l"(d) : "l"(a), "l"(b));
}

// ---------------------------------------------------------------------------
// Build the three gaussian kernels (ks = 91, 481, 1501), deterministic tree
// reduction for normalization. Also zeroes the loss accumulators.
// ---------------------------------------------------------------------------
__global__ void init_kernels_k() {
    __shared__ float red[1024];
    const float sig[3] = {15.f, 80.f, 250.f};
    const int   ks [3] = {91, 481, 1501};
    const int   off[3] = {0, 128, 640};
    int tid = threadIdx.x;
    if (tid < 4) g_red[tid] = 0.f;
    for (int s = 0; s < 3; ++s) {
        int n = ks[s];
        float c   = 0.5f * (float)(n - 1);
        float inv = 1.0f / sig[s];
        float local = 0.f;
        for (int t = tid; t < n; t += 1024) {
            float x = ((float)t - c) * inv;
            float v = expf(-0.5f * x * x);
            g_kern[off[s] + t] = v;
            local += v;
        }
        red[tid] = local;
        __syncthreads();
        for (int st = 512; st > 0; st >>= 1) {
            if (tid < st) red[tid] += red[tid + st];
            __syncthreads();
        }
        float s_inv = 1.0f / red[0];
        __syncthreads();
        for (int t = tid; t < n; t += 1024) g_kern[off[s] + t] *= s_inv;
    }
}

__device__ __forceinline__ int reflect_idx(int s) {
    return (s < 0) ? -s : ((s >= HH) ? (2*HH - 2 - s) : s);
}

// ---------------------------------------------------------------------------
// Separable conv pass, f32x2 packed, output-stationary with a PF-deep
// prefetch queue. Each thread owns TWO adjacent fast-dim columns.
//
//   - 16 packed accumulators, 16-deep circular window (registers)
//   - pf[8]: rows prefetched 8 taps ahead; window refill is a register move,
//     so the LDG latency is 8 taps (~170 issue slots) from its consumer.
//   - shared table skp[t/2] = float4 {k_t, byteoff_t, k_{t+1}, byteoff_{t+1}}
//     where byteoff_t addresses the refill row (t + RPT + PF), reflect-applied
//     per block. One LDS.128 per two taps, no dependency on loop state.
//
// Tap loop runs over kpad = ceil(ks/16)*16 taps, kernel zero-padded (padded
// taps are exact no-ops). Max touched source row = o0-p+kpad+RPT+PF-1
// = 1008-750+1504+23 = 1785 < 2046: single reflection always valid.
//
// PASS==1: in = clip(input) [img][y][x], conv over y, out -> g_tmpT[img][x][y]
// PASS==2: in = g_tmpT      [img][x][y], conv over x, out -> g_acc  [img][y][x]
//          epilogue: acc (=|first) / (+=) log(max(blur, eps))
// ---------------------------------------------------------------------------
template<int PASS>
__global__ void __launch_bounds__(128, 4) conv_k(const float* __restrict__ din,
                                                 int koff, int ks, int p, int first)
{
    __shared__ float4 skp[760];          // kpad/2 <= 752 entries
    int kpad = (ks + RPT - 1) & ~(RPT - 1);
    int tid = threadIdx.x;
    int o0  = blockIdx.y * RPT;          // slow-dim tile base
    for (int t = tid; t < kpad / 2; t += 128) {
        int t0 = 2 * t, t1 = 2 * t + 1;
        float k0 = (t0 < ks) ? g_kern[koff + t0] : 0.f;
        float k1 = (t1 < ks) ? g_kern[koff + t1] : 0.f;
        int s0 = reflect_idx(o0 - p + t0 + RPT + PF);
        int s1 = reflect_idx(o0 - p + t1 + RPT + PF);
        skp[t] = make_float4(k0, __int_as_float(s0 * (WW * 4)),
                             k1, __int_as_float(s1 * (WW * 4)));
    }
    __syncthreads();

    int l   = blockIdx.x * 128 + tid;    // fast-dim pair index (cols 2l, 2l+1)
    int img = blockIdx.z;
    const float* __restrict__ base =
        (PASS == 1) ? (din + (size_t)img * HW) : (g_tmpT + (size_t)img * HW);
    const char* bp = (const char*)base + (size_t)l * 8;   // +8B for the pair

    unsigned long long acc2[RPT], win2[RPT], pf2[PF];
#pragma unroll
    for (int r = 0; r < RPT; ++r) acc2[r] = 0ull;

    // preload window (rows 0..15 rel. o0-p) and prefetch queue (rows 16..23)
#pragma unroll
    for (int i = 0; i < RPT + PF; ++i) {
        int s = reflect_idx(o0 - p + i);
        float2 v = __ldg((const float2*)(bp + (size_t)s * (WW * 4)));
        if (PASS == 1) {
            v.x = fminf(fmaxf(v.x, EPSF), 1.0f);
            v.y = fminf(fmaxf(v.y, EPSF), 1.0f);
        }
        if (i < RPT) win2[i] = pk(v.x, v.y);
        else         pf2[i - RPT] = pk(v.x, v.y);
    }

    for (int t = 0; t < kpad; t += RPT) {
#pragma unroll
        for (int h = 0; h < RPT / 2; ++h) {          // 2 taps per iteration
            float4 e = skp[(t >> 1) + h];            // one LDS.128, hoistable
            int j0 = 2 * h, j1 = 2 * h + 1;
            {
                unsigned long long kk = pk(e.x, e.x);
#pragma unroll
                for (int r = 0; r < RPT; ++r)
                    ffma2(acc2[r], kk, win2[(r + j0) & (RPT - 1)]);
                win2[j0] = pf2[j0 & (PF - 1)];
                float2 v = __ldg((const float2*)(bp + __float_as_int(e.y)));
                if (PASS == 1) {
                    v.x = fminf(fmaxf(v.x, EPSF), 1.0f);
                    v.y = fminf(fmaxf(v.y, EPSF), 1.0f);
                }
                pf2[j0 & (PF - 1)] = pk(v.x, v.y);
            }
            {
                unsigned long long kk = pk(e.z, e.z);
#pragma unroll
                for (int r = 0; r < RPT; ++r)
                    ffma2(acc2[r], kk, win2[(r + j1) & (RPT - 1)]);
                win2[j1] = pf2[j1 & (PF - 1)];
                float2 v = __ldg((const float2*)(bp + __float_as_int(e.w)));
                if (PASS == 1) {
                    v.x = fminf(fmaxf(v.x, EPSF), 1.0f);
                    v.y = fminf(fmaxf(v.y, EPSF), 1.0f);
                }
                pf2[j1 & (PF - 1)] = pk(v.x, v.y);
            }
        }
    }

    if (PASS == 1) {
        // tmpT[img][x][y]: col pair x = 2l, 2l+1; y = o0+r (two 64B runs)
        float* oa = g_tmpT + (size_t)img * HW + (size_t)(2 * l)     * HH + o0;
        float* ob = g_tmpT + (size_t)img * HW + (size_t)(2 * l + 1) * HH + o0;
#pragma unroll
        for (int r = 0; r < RPT; ++r) {
            float2 v = unpk(acc2[r]);
            oa[r] = v.x;
            ob[r] = v.y;
        }
    } else {
        // NORMAL layout: g_acc[img][y][x], y pair = 2l, 2l+1; x = o0+r
        float* oa = g_acc + (size_t)img * HW + (size_t)(2 * l)     * WW + o0;
        float* ob = g_acc + (size_t)img * HW + (size_t)(2 * l + 1) * WW + o0;
        if (first) {
#pragma unroll
            for (int r = 0; r < RPT; ++r) {
                float2 v = unpk(acc2[r]);
                oa[r] = logf(fmaxf(v.x, EPSF));
                ob[r] = logf(fmaxf(v.y, EPSF));
            }
        } else {
#pragma unroll
            for (int r = 0; r < RPT; ++r) {
                float2 v = unpk(acc2[r]);
                oa[r] += logf(fmaxf(v.x, EPSF));
                ob[r] += logf(fmaxf(v.y, EPSF));
            }
        }
    }
}

// ---------------------------------------------------------------------------
// Emit reflectance and illumination (NCHW) into d_out. Fully coalesced.
// reflectance = log(clip(in,eps,1)) - acc/3 ; illumination = log(max(in,eps)) - refl
// ---------------------------------------------------------------------------
__global__ void fields_k(const float* __restrict__ inp, float* __restrict__ dout) {
    int total = NIMG * HW;
    for (int idx = blockIdx.x * blockDim.x + threadIdx.x; idx < total;
         idx += gridDim.x * blockDim.x) {
        float a  = g_acc[idx];
        float ib = a * (1.0f / 3.0f);
        float v  = inp[idx];
        float li = logf(fminf(fmaxf(v, EPSF), 1.0f));
        float refl  = li - ib;
        float illum = logf(fmaxf(v, EPSF)) - refl;
        dout[3 + idx]          = refl;
        dout[3 + total + idx]  = illum;
    }
}

// ---------------------------------------------------------------------------
// Gradient-magnitude sums for both fields (reads d_out, L2-hot).
// ---------------------------------------------------------------------------
__global__ void grad_k(const float* __restrict__ dout) {
    const float* __restrict__ refl = dout + 3;
    const float* __restrict__ ill  = dout + 3 + NIMG * HW;
    float s0 = 0.f, s1 = 0.f, s2 = 0.f, s3 = 0.f;
    int total = NIMG * HW;
    for (int idx = blockIdx.x * blockDim.x + threadIdx.x; idx < total;
         idx += gridDim.x * blockDim.x) {
        int x = idx & 1023;
        int y = (idx >> 10) & 1023;
        float r0 = refl[idx], i0 = ill[idx];
        if (x < 1023) {
            s0 += fabsf(r0 - refl[idx + 1]);
            s2 += fabsf(i0 - ill[idx + 1]);
        }
        if (y < 1023) {
            s1 += fabsf(r0 - refl[idx + 1024]);
            s3 += fabsf(i0 - ill[idx + 1024]);
        }
    }
#pragma unroll
    for (int o = 16; o > 0; o >>= 1) {
        s0 += __shfl_down_sync(0xffffffffu, s0, o);
        s1 += __shfl_down_sync(0xffffffffu, s1, o);
        s2 += __shfl_down_sync(0xffffffffu, s2, o);
        s3 += __shfl_down_sync(0xffffffffu, s3, o);
    }
    __shared__ float sb[4][8];
    int wid = threadIdx.x >> 5, lid = threadIdx.x & 31;
    if (lid == 0) { sb[0][wid] = s0; sb[1][wid] = s1; sb[2][wid] = s2; sb[3][wid] = s3; }
    __syncthreads();
    if (threadIdx.x == 0) {
        float t0 = 0.f, t1 = 0.f, t2 = 0.f, t3 = 0.f;
        int nw = blockDim.x >> 5;
        for (int w = 0; w < nw; ++w) {
            t0 += sb[0][w]; t1 += sb[1][w]; t2 += sb[2][w]; t3 += sb[3][w];
        }
        atomicAdd(&g_red[0], t0); atomicAdd(&g_red[1], t1);
        atomicAdd(&g_red[2], t2); atomicAdd(&g_red[3], t3);
    }
}

__global__ void fin_k(float* dout) {
    if (threadIdx.x == 0) {
        float ngx = (float)(NIMG * HH * (WW - 1));
        float ngy = (float)(NIMG * (HH - 1) * WW);
        float ld = g_red[0] / ngx + g_red[1] / ngy;
        float ls = g_red[2] / ngx + g_red[3] / ngy;
        dout[0] = ls;      // DETAIL_WEIGHT = 0, ILLUM_WEIGHT = 1
        dout[1] = ld;
        dout[2] = ls;
    }
}

extern "C" void kernel_launch(void* const* d_in, const int* in_sizes, int n_in,
                              void* d_out, int out_size) {
    const float* inp = (const float*)d_in[0];
    float* out = (float*)d_out;

    init_kernels_k<<<1, 1024>>>();

    const int ks [3] = {91, 481, 1501};
    const int off[3] = {0, 128, 640};
    const int pp [3] = {45, 240, 750};
    dim3 gconv(WW / 256, HH / RPT, NIMG);   // 4 x 64 x 6 = 1536 blocks
    for (int s = 0; s < 3; ++s) {
        conv_k<1><<<gconv, 128>>>(inp, off[s], ks[s], pp[s], 0);
        conv_k<2><<<gconv, 128>>>(inp, off[s], ks[s], pp[s], s == 0);
    }

    fields_k<<<4096, 256>>>(inp, out);
    grad_k<<<2048, 256>>>(out);
    fin_k<<<1, 32>>>(out);
}

// round 10
// speedup vs baseline: 1.9944x; 1.6249x over previous
#include <cuda_runtime.h>
#include <cuda_bf16.h>
#include <cstdint>
#include <math.h>

#define HH 1024
#define NIMG 6
#define HW (HH*HH)
#define EPSF 1e-3f

typedef unsigned short u16;
typedef unsigned int u32;

// ---------------- device scratch (allocation-free rule) ---------------------
__device__ u16 g_Ah[3*HW];       // blur matrices, bf16 hi, [sigma][i][j]
__device__ u16 g_Al[3*HW];       // lo
__device__ u16 g_XTh[NIMG*HW];   // clipped input transposed [img][x][u], hi
__device__ u16 g_XTl[NIMG*HW];   // lo
__device__ u16 g_Yh[NIMG*HW];    // vertical blur [img][y][v], hi
__device__ u16 g_Yl[NIMG*HW];    // lo
__device__ float g_acc[NIMG*HW]; // sum log(blur) [img][y][x]
__device__ float g_kern[2304];   // 1D kernels at offsets 0,128,640
__device__ float g_red[4];

__device__ __forceinline__ u32 smem_u32(const void* p) {
    u32 a;
    asm("{ .reg .u64 t; cvta.to.shared.u64 t, %1; cvt.u32.u64 %0, t; }" : "=r"(a) : "l"(p));
    return a;
}
#define LDSM4(r, addr) asm volatile( \
    "ldmatrix.sync.aligned.m8n8.x4.shared.b16 {%0,%1,%2,%3}, [%4];" \
    : "=r"((r)[0]),"=r"((r)[1]),"=r"((r)[2]),"=r"((r)[3]) : "r"(addr))
#define MMA16816(dd, aa, b0, b1) asm volatile( \
    "mma.sync.aligned.m16n8k16.row.col.f32.bf16.bf16.f32 " \
    "{%0,%1,%2,%3},{%4,%5,%6,%7},{%8,%9},{%0,%1,%2,%3};" \
    : "+f"((dd)[0]),"+f"((dd)[1]),"+f"((dd)[2]),"+f"((dd)[3]) \
    : "r"((aa)[0]),"r"((aa)[1]),"r"((aa)[2]),"r"((aa)[3]), "r"(b0), "r"(b1))

__device__ __forceinline__ u16 bf_hi(float v) {
    return __bfloat16_as_ushort(__float2bfloat16(v));
}
__device__ __forceinline__ void bf_split(float v, u16& h, u16& l) {
    __nv_bfloat16 bh = __float2bfloat16(v);
    h = __bfloat16_as_ushort(bh);
    l = __bfloat16_as_ushort(__float2bfloat16(v - __bfloat162float(bh)));
}

// ---------------------------------------------------------------------------
// 1D gaussian kernels (ks = 91, 481, 1501), deterministic normalization.
// ---------------------------------------------------------------------------
__global__ void init_kernels_k() {
    __shared__ float red[1024];
    const float sig[3] = {15.f, 80.f, 250.f};
    const int   ks [3] = {91, 481, 1501};
    const int   off[3] = {0, 128, 640};
    int tid = threadIdx.x;
    if (tid < 4) g_red[tid] = 0.f;
    for (int s = 0; s < 3; ++s) {
        int n = ks[s];
        float c = 0.5f * (float)(n - 1), inv = 1.0f / sig[s], local = 0.f;
        for (int t = tid; t < n; t += 1024) {
            float x = ((float)t - c) * inv;
            float v = expf(-0.5f * x * x);
            g_kern[off[s] + t] = v;
            local += v;
        }
        red[tid] = local;
        __syncthreads();
        for (int st = 512; st > 0; st >>= 1) {
            if (tid < st) red[tid] += red[tid + st];
            __syncthreads();
        }
        float s_inv = 1.0f / red[0];
        __syncthreads();
        for (int t = tid; t < n; t += 1024) g_kern[off[s] + t] *= s_inv;
    }
}

// ---------------------------------------------------------------------------
// Exact reflect-pad blur matrix, split bf16 hi/lo.
// A[i][j] = kt(j-i+p) + [j>0] kt(-j-i+p) + [j<1023] kt(2046-j-i+p)
// Row support is contiguous: [i-p, i+p] clamped -> banded K-ranges are exact.
// ---------------------------------------------------------------------------
__global__ void buildA_k() {
    const int ks [3] = {91, 481, 1501};
    const int off[3] = {0, 128, 640};
    const int pp [3] = {45, 240, 750};
    int i = blockIdx.x, s = blockIdx.y;
    int koff = off[s], kn = ks[s], p = pp[s];
    size_t base = (size_t)s * HW + (size_t)i * 1024;
    for (int j = threadIdx.x; j < 1024; j += blockDim.x) {
        float v = 0.f;
        int t0 = j - i + p;
        if (t0 >= 0 && t0 < kn) v += g_kern[koff + t0];
        int t1 = -j - i + p;
        if (j > 0 && t1 >= 0 && t1 < kn) v += g_kern[koff + t1];
        int t2 = 2046 - j - i + p;
        if (j < 1023 && t2 >= 0 && t2 < kn) v += g_kern[koff + t2];
        u16 h, l;
        bf_split(v, h, l);
        g_Ah[base + j] = h;
        g_Al[base + j] = l;
    }
}

// ---------------------------------------------------------------------------
// Clip input, split to bf16 hi/lo, write TRANSPOSED [img][x][u].
// ---------------------------------------------------------------------------
__global__ void splitX_k(const float* __restrict__ inp) {
    __shared__ float sm[32][33];
    int x0 = blockIdx.x * 32, y0 = blockIdx.y * 32, img = blockIdx.z;
    int tx = threadIdx.x, ty = threadIdx.y;
    float v = inp[(size_t)img * HW + (size_t)(y0 + ty) * 1024 + x0 + tx];
    sm[ty][tx] = fminf(fmaxf(v, EPSF), 1.0f);
    __syncthreads();
    float w = sm[tx][ty];
    u16 h, l;
    bf_split(w, h, l);
    size_t o = (size_t)img * HW + (size_t)(x0 + ty) * 1024 + y0 + tx;
    g_XTh[o] = h;
    g_XTl[o] = l;
}

// ---------------------------------------------------------------------------
// Banded GEMM on legacy tensor path (mma.sync m16n8k16 bf16, base-ISA).
// D[M x N] = P(M x K) . Q(N x K)^T, K restricted to the gaussian band.
// bf16x3: D = Ph.Qh + Ph.Ql + Pl.Qh accumulated into one fp32 fragment.
//
// Block: 512 thr = 16 warps (2 M-warps x 8 N-warps); warp tile m64 x n32;
// block tile M=128, N=256; K-slab 32. smem rows padded to 80B (stride 5
// 16B-granules -> ldmatrix 8-row access conflict-free: 5r+g mod 8 bijective).
//
// PASS==1: P=(Ah,Al) rows y (band from m0), Q=(XTh,XTl) rows img*1024+x.
//          epilogue: split D to (g_Yh, g_Yl) at [img][y][x].
// PASS==2: P=(Yh,Yl) rows img*1024+y, Q=(Ah,Al) rows x (band from n0).
//          epilogue: g_acc = / += log(max(D, eps)).
// ---------------------------------------------------------------------------
#define SMEM_MMA 61440
template<int PASS>
__global__ void __launch_bounds__(512, 1) mma_k(
    const u16* __restrict__ Ph, const u16* __restrict__ Pl,
    const u16* __restrict__ Qh, const u16* __restrict__ Ql,
    int p, int first)
{
    extern __shared__ char sm[];
    const int SPH = 0, SPL = 10240, SQH = 20480, SQL = 40960;
    u32 sb = smem_u32(sm);
    int tid = threadIdx.x, wid = tid >> 5, l = tid & 31;
    int wm = wid >> 3, wn = wid & 7;

    int m0 = blockIdx.x * 128, n0 = blockIdx.y * 256;
    int c0   = (PASS == 1) ? m0 : n0;
    int cext = (PASS == 1) ? 128 : 256;
    int kmin = max(0, c0 - p) & ~31;
    int kmax = min(1024, (c0 + cext + p + 31) & ~31);

    float d[16][4];
#pragma unroll
    for (int i = 0; i < 16; ++i)
#pragma unroll
        for (int j = 0; j < 4; ++j) d[i][j] = 0.f;

    // ldmatrix per-lane offsets (rows x 80B, 16B granules)
    u32 aoff = (u32)(((l & 7) + ((l >> 3) & 1) * 8) * 80 + (l >> 4) * 16);
    u32 boff = (u32)(((l & 7) + ((l >> 4) & 1) * 8) * 80 + ((l >> 3) & 1) * 16);
    u32 aPh = sb + SPH + wm * (64 * 80) + aoff;
    u32 aPl = sb + SPL + wm * (64 * 80) + aoff;
    u32 bQh = sb + SQH + wn * (32 * 80) + boff;
    u32 bQl = sb + SQL + wn * (32 * 80) + boff;

    int prow = tid >> 2, pg = tid & 3;

    for (int k0 = kmin; k0 < kmax; k0 += 32) {
        __syncthreads();
        {   // stage K-slab: P 128x64B, Q 256x64B, hi+lo
            size_t srcP = ((size_t)(m0 + prow) * 1024 + k0) * 2 + pg * 16;
            *(uint4*)(sm + SPH + prow * 80 + pg * 16) = *(const uint4*)((const char*)Ph + srcP);
            *(uint4*)(sm + SPL + prow * 80 + pg * 16) = *(const uint4*)((const char*)Pl + srcP);
#pragma unroll
            for (int q = 0; q < 2; ++q) {
                int it = tid + q * 512;
                int qrow = it >> 2, qg = it & 3;
                size_t srcQ = ((size_t)(n0 + qrow) * 1024 + k0) * 2 + qg * 16;
                *(uint4*)(sm + SQH + qrow * 80 + qg * 16) = *(const uint4*)((const char*)Qh + srcQ);
                *(uint4*)(sm + SQL + qrow * 80 + qg * 16) = *(const uint4*)((const char*)Ql + srcQ);
            }
        }
        __syncthreads();
#pragma unroll
        for (int kb = 0; kb < 2; ++kb) {
            u32 a[4][4], b1[2][4], b2[2][4];
#pragma unroll
            for (int mi = 0; mi < 4; ++mi) LDSM4(a[mi], aPh + mi * (16 * 80) + kb * 32);
#pragma unroll
            for (int nj = 0; nj < 2; ++nj) LDSM4(b1[nj], bQh + nj * (16 * 80) + kb * 32);
#pragma unroll
            for (int mi = 0; mi < 4; ++mi)
#pragma unroll
                for (int ni = 0; ni < 4; ++ni)
                    MMA16816(d[mi * 4 + ni], a[mi], b1[ni >> 1][(ni & 1) * 2], b1[ni >> 1][(ni & 1) * 2 + 1]);
#pragma unroll
            for (int nj = 0; nj < 2; ++nj) LDSM4(b2[nj], bQl + nj * (16 * 80) + kb * 32);
#pragma unroll
            for (int mi = 0; mi < 4; ++mi)
#pragma unroll
                for (int ni = 0; ni < 4; ++ni)
                    MMA16816(d[mi * 4 + ni], a[mi], b2[ni >> 1][(ni & 1) * 2], b2[ni >> 1][(ni & 1) * 2 + 1]);
#pragma unroll
            for (int mi = 0; mi < 4; ++mi) LDSM4(a[mi], aPl + mi * (16 * 80) + kb * 32);  // reuse regs
#pragma unroll
            for (int mi = 0; mi < 4; ++mi)
#pragma unroll
                for (int ni = 0; ni < 4; ++ni)
                    MMA16816(d[mi * 4 + ni], a[mi], b1[ni >> 1][(ni & 1) * 2], b1[ni >> 1][(ni & 1) * 2 + 1]);
        }
    }

    // epilogue: d-frag thread map: rows t/4 (+8), cols (t%4)*2 (+1)
#pragma unroll
    for (int mi = 0; mi < 4; ++mi) {
#pragma unroll
        for (int ni = 0; ni < 4; ++ni) {
            float* dd = d[mi * 4 + ni];
            int gm0 = m0 + wm * 64 + mi * 16 + (l >> 2);
            int gc  = n0 + wn * 32 + ni * 8 + (l & 3) * 2;
#pragma unroll
            for (int h = 0; h < 2; ++h) {
                int gm = gm0 + h * 8;
                float v0 = dd[h * 2 + 0], v1 = dd[h * 2 + 1];
                if (PASS == 1) {
                    // out addr: img = gc>>10, x = gc&1023 -> [img][gm][x]
                    size_t o = ((size_t)(gc >> 10)) * HW + (size_t)gm * 1024 + (gc & 1023);
                    u16 h0, l0, h1, l1;
                    bf_split(v0, h0, l0);
                    bf_split(v1, h1, l1);
                    *(u32*)&g_Yh[o] = (u32)h0 | ((u32)h1 << 16);
                    *(u32*)&g_Yl[o] = (u32)l0 | ((u32)l1 << 16);
                } else {
                    size_t o = (size_t)gm * 1024 + gc;   // gm = img*1024+y
                    float r0 = logf(fmaxf(v0, EPSF));
                    float r1 = logf(fmaxf(v1, EPSF));
                    if (!first) { r0 += g_acc[o]; r1 += g_acc[o + 1]; }
                    g_acc[o]     = r0;
                    g_acc[o + 1] = r1;
                }
            }
        }
    }
}

// ---------------------------------------------------------------------------
// reflectance / illumination fields + loss reductions (unchanged).
// ---------------------------------------------------------------------------
__global__ void fields_k(const float* __restrict__ inp, float* __restrict__ dout) {
    int total = NIMG * HW;
    for (int idx = blockIdx.x * blockDim.x + threadIdx.x; idx < total;
         idx += gridDim.x * blockDim.x) {
        float ib = g_acc[idx] * (1.0f / 3.0f);
        float v  = inp[idx];
        float li = logf(fminf(fmaxf(v, EPSF), 1.0f));
        float refl  = li - ib;
        float illum = logf(fmaxf(v, EPSF)) - refl;
        dout[3 + idx]         = refl;
        dout[3 + total + idx] = illum;
    }
}

__global__ void grad_k(const float* __restrict__ dout) {
    const float* __restrict__ refl = dout + 3;
    const float* __restrict__ ill  = dout + 3 + NIMG * HW;
    float s0 = 0.f, s1 = 0.f, s2 = 0.f, s3 = 0.f;
    int total = NIMG * HW;
    for (int idx = blockIdx.x * blockDim.x + threadIdx.x; idx < total;
         idx += gridDim.x * blockDim.x) {
        int x = idx & 1023, y = (idx >> 10) & 1023;
        float r0 = refl[idx], i0 = ill[idx];
        if (x < 1023) { s0 += fabsf(r0 - refl[idx + 1]);    s2 += fabsf(i0 - ill[idx + 1]); }
        if (y < 1023) { s1 += fabsf(r0 - refl[idx + 1024]); s3 += fabsf(i0 - ill[idx + 1024]); }
    }
#pragma unroll
    for (int o = 16; o > 0; o >>= 1) {
        s0 += __shfl_down_sync(0xffffffffu, s0, o);
        s1 += __shfl_down_sync(0xffffffffu, s1, o);
        s2 += __shfl_down_sync(0xffffffffu, s2, o);
        s3 += __shfl_down_sync(0xffffffffu, s3, o);
    }
    __shared__ float sb[4][8];
    int wid = threadIdx.x >> 5, lid = threadIdx.x & 31;
    if (lid == 0) { sb[0][wid] = s0; sb[1][wid] = s1; sb[2][wid] = s2; sb[3][wid] = s3; }
    __syncthreads();
    if (threadIdx.x == 0) {
        float t0 = 0.f, t1 = 0.f, t2 = 0.f, t3 = 0.f;
        int nw = blockDim.x >> 5;
        for (int w = 0; w < nw; ++w) { t0 += sb[0][w]; t1 += sb[1][w]; t2 += sb[2][w]; t3 += sb[3][w]; }
        atomicAdd(&g_red[0], t0); atomicAdd(&g_red[1], t1);
        atomicAdd(&g_red[2], t2); atomicAdd(&g_red[3], t3);
    }
}

__global__ void fin_k(float* dout) {
    if (threadIdx.x == 0) {
        float ngx = (float)(NIMG * 1024 * 1023);
        float ngy = (float)(NIMG * 1023 * 1024);
        float ld = g_red[0] / ngx + g_red[1] / ngy;
        float ls = g_red[2] / ngx + g_red[3] / ngy;
        dout[0] = ls; dout[1] = ld; dout[2] = ls;   // DETAIL_W=0, ILLUM_W=1
    }
}

extern "C" void kernel_launch(void* const* d_in, const int* in_sizes, int n_in,
                              void* d_out, int out_size) {
    const float* inp = (const float*)d_in[0];
    float* out = (float*)d_out;

    cudaFuncSetAttribute(mma_k<1>, cudaFuncAttributeMaxDynamicSharedMemorySize, SMEM_MMA);
    cudaFuncSetAttribute(mma_k<2>, cudaFuncAttributeMaxDynamicSharedMemorySize, SMEM_MMA);

    init_kernels_k<<<1, 1024>>>();
    buildA_k<<<dim3(1024, 3), 256>>>();
    splitX_k<<<dim3(32, 32, NIMG), dim3(32, 32)>>>(inp);

    // device-symbol addresses are identical in device code; pass via kernels
    // using the symbols directly is not possible for args, so fetch once:
    static u16 *pAh = nullptr, *pAl, *pXTh, *pXTl, *pYh, *pYl;
    if (!pAh) {
        cudaGetSymbolAddress((void**)&pAh,  g_Ah);
        cudaGetSymbolAddress((void**)&pAl,  g_Al);
        cudaGetSymbolAddress((void**)&pXTh, g_XTh);
        cudaGetSymbolAddress((void**)&pXTl, g_XTl);
        cudaGetSymbolAddress((void**)&pYh,  g_Yh);
        cudaGetSymbolAddress((void**)&pYl,  g_Yl);
    }

    const int pp[3] = {45, 240, 750};
    for (int s = 0; s < 3; ++s) {
        mma_k<1><<<dim3(8, 24), 512, SMEM_MMA>>>(
            pAh + (size_t)s * HW, pAl + (size_t)s * HW, pXTh, pXTl, pp[s], 0);
        mma_k<2><<<dim3(48, 4), 512, SMEM_MMA>>>(
            pYh, pYl, pAh + (size_t)s * HW, pAl + (size_t)s * HW, pp[s], s == 0);
    }

    fields_k<<<4096, 256>>>(inp, out);
    grad_k<<<2048, 256>>>(out);
    fin_k<<<1, 32>>>(out);
}

// round 11
// speedup vs baseline: 2.6055x; 1.3064x over previous
#include <cuda_runtime.h>
#include <cuda_bf16.h>
#include <cstdint>
#include <math.h>

#define HH 1024
#define NIMG 6
#define HW (HH*HH)
#define EPSF 1e-3f

typedef unsigned short u16;
typedef unsigned int u32;

// ---------------- device scratch (allocation-free rule) ---------------------
__device__ u16 g_Ah[3*HW];          // blur matrices, bf16 hi, [sigma][i][j]
__device__ u16 g_Al[3*HW];          // lo
__device__ u16 g_XTh[NIMG*HW];      // clipped input transposed [img][x][u], hi
__device__ u16 g_XTl[NIMG*HW];      // lo
__device__ u16 g_Yh[3*NIMG*HW];     // vertical blur [sigma][img][y][x], hi
__device__ u16 g_Yl[3*NIMG*HW];     // lo
__device__ float g_accS[3*NIMG*HW]; // log(blur_sigma) [sigma][img][y][x]
__device__ float g_kern[2304];      // 1D kernels at offsets 0,128,640
__device__ float g_red[4];

__constant__ int c_p[3] = {45, 240, 750};

__device__ __forceinline__ u32 smem_u32(const void* p) {
    u32 a;
    asm("{ .reg .u64 t; cvta.to.shared.u64 t, %1; cvt.u32.u64 %0, t; }" : "=r"(a) : "l"(p));
    return a;
}
#define LDSM4(r, addr) asm volatile( \
    "ldmatrix.sync.aligned.m8n8.x4.shared.b16 {%0,%1,%2,%3}, [%4];" \
    : "=r"((r)[0]),"=r"((r)[1]),"=r"((r)[2]),"=r"((r)[3]) : "r"(addr))
#define MMA16816(dd, aa, b0, b1) asm volatile( \
    "mma.sync.aligned.m16n8k16.row.col.f32.bf16.bf16.f32 " \
    "{%0,%1,%2,%3},{%4,%5,%6,%7},{%8,%9},{%0,%1,%2,%3};" \
    : "+f"((dd)[0]),"+f"((dd)[1]),"+f"((dd)[2]),"+f"((dd)[3]) \
    : "r"((aa)[0]),"r"((aa)[1]),"r"((aa)[2]),"r"((aa)[3]), "r"(b0), "r"(b1))
#define CP16(dst, src)  asm volatile("cp.async.cg.shared.global [%0], [%1], 16;" :: "r"(dst), "l"(src))
#define CP_COMMIT()     asm volatile("cp.async.commit_group;" ::: "memory")
#define CP_WAIT0()      asm volatile("cp.async.wait_group 0;" ::: "memory")
#define CP_WAIT1()      asm volatile("cp.async.wait_group 1;" ::: "memory")

__device__ __forceinline__ void bf_split(float v, u16& h, u16& l) {
    __nv_bfloat16 bh = __float2bfloat16(v);
    h = __bfloat16_as_ushort(bh);
    l = __bfloat16_as_ushort(__float2bfloat16(v - __bfloat162float(bh)));
}

// ---------------------------------------------------------------------------
__global__ void init_kernels_k() {
    __shared__ float red[1024];
    const float sig[3] = {15.f, 80.f, 250.f};
    const int   ks [3] = {91, 481, 1501};
    const int   off[3] = {0, 128, 640};
    int tid = threadIdx.x;
    if (tid < 4) g_red[tid] = 0.f;
    for (int s = 0; s < 3; ++s) {
        int n = ks[s];
        float c = 0.5f * (float)(n - 1), inv = 1.0f / sig[s], local = 0.f;
        for (int t = tid; t < n; t += 1024) {
            float x = ((float)t - c) * inv;
            float v = expf(-0.5f * x * x);
            g_kern[off[s] + t] = v;
            local += v;
        }
        red[tid] = local;
        __syncthreads();
        for (int st = 512; st > 0; st >>= 1) {
            if (tid < st) red[tid] += red[tid + st];
            __syncthreads();
        }
        float s_inv = 1.0f / red[0];
        __syncthreads();
        for (int t = tid; t < n; t += 1024) g_kern[off[s] + t] *= s_inv;
    }
}

// ---------------------------------------------------------------------------
// Exact reflect-pad blur matrix, split bf16 hi/lo.
// A[i][j] = kt(j-i+p) + [j>0] kt(-j-i+p) + [j<1023] kt(2046-j-i+p)
// ---------------------------------------------------------------------------
__global__ void buildA_k() {
    const int ks [3] = {91, 481, 1501};
    const int off[3] = {0, 128, 640};
    const int pp [3] = {45, 240, 750};
    int i = blockIdx.x, s = blockIdx.y;
    int koff = off[s], kn = ks[s], p = pp[s];
    size_t base = (size_t)s * HW + (size_t)i * 1024;
    for (int j = threadIdx.x; j < 1024; j += blockDim.x) {
        float v = 0.f;
        int t0 = j - i + p;
        if (t0 >= 0 && t0 < kn) v += g_kern[koff + t0];
        int t1 = -j - i + p;
        if (j > 0 && t1 >= 0 && t1 < kn) v += g_kern[koff + t1];
        int t2 = 2046 - j - i + p;
        if (j < 1023 && t2 >= 0 && t2 < kn) v += g_kern[koff + t2];
        u16 h, l;
        bf_split(v, h, l);
        g_Ah[base + j] = h;
        g_Al[base + j] = l;
    }
}

__global__ void splitX_k(const float* __restrict__ inp) {
    __shared__ float sm[32][33];
    int x0 = blockIdx.x * 32, y0 = blockIdx.y * 32, img = blockIdx.z;
    int tx = threadIdx.x, ty = threadIdx.y;
    float v = inp[(size_t)img * HW + (size_t)(y0 + ty) * 1024 + x0 + tx];
    sm[ty][tx] = fminf(fmaxf(v, EPSF), 1.0f);
    __syncthreads();
    float w = sm[tx][ty];
    u16 h, l;
    bf_split(w, h, l);
    size_t o = (size_t)img * HW + (size_t)(x0 + ty) * 1024 + y0 + tx;
    g_XTh[o] = h;
    g_XTl[o] = l;
}

// ---------------------------------------------------------------------------
// Banded bf16x3 GEMM on mma.sync (base-ISA HMMA), 2-stage cp.async pipeline.
// D[M x N] = P(M x K) . Q(N x K)^T, K limited to the gaussian band.
// Block 512 thr = 16 warps (2 M x 8 N), block tile M=128 N=256, K-slab 32.
// smem: {Phi, Plo, Qhi, Qlo} x 2 buffers; rows padded to 80B (conflict-free).
//
// PASS==1: sigma=bx%3, P=A_sigma rows y, Q=XT rows img*1024+x -> Y[sigma]
// PASS==2: sigma=bx%3, P=Y[sigma] rows img*1024+y, Q=A_sigma rows x
//          -> g_accS[sigma] = log(max(D, eps))
// ---------------------------------------------------------------------------
#define SPH 0
#define SPL 10240
#define SQH 20480
#define SQL 40960
#define BUF 61440
#define SMEM_MMA (2*BUF)

template<int PASS>
__device__ __forceinline__ void stage_slab(u32 sa, const u16* Ph, const u16* Pl,
                                           const u16* Qh, const u16* Ql,
                                           int m0, int n0, int k0, int tid) {
    int prow = tid >> 2, pg = tid & 3;
    size_t srcP = ((size_t)(m0 + prow) * 1024 + k0) * 2 + pg * 16;
    CP16(sa + SPH + prow * 80 + pg * 16, (const char*)Ph + srcP);
    CP16(sa + SPL + prow * 80 + pg * 16, (const char*)Pl + srcP);
#pragma unroll
    for (int q = 0; q < 2; ++q) {
        int it = tid + q * 512;
        int qrow = it >> 2, qg = it & 3;
        size_t srcQ = ((size_t)(n0 + qrow) * 1024 + k0) * 2 + qg * 16;
        CP16(sa + SQH + qrow * 80 + qg * 16, (const char*)Qh + srcQ);
        CP16(sa + SQL + qrow * 80 + qg * 16, (const char*)Ql + srcQ);
    }
}

template<int PASS>
__global__ void __launch_bounds__(512, 1) mma_k() {
    extern __shared__ char sm[];
    u32 sb = smem_u32(sm);
    int tid = threadIdx.x, wid = tid >> 5, l = tid & 31;
    int wm = wid >> 3, wn = wid & 7;

    int sigma = blockIdx.x % 3;
    int blk   = blockIdx.x / 3;
    int p = c_p[sigma];
    int m0, n0;
    const u16 *Ph, *Pl, *Qh, *Ql;
    if (PASS == 1) {
        m0 = blk * 128;               // y rows of A
        n0 = blockIdx.y * 256;        // img*1024 + x
        Ph = g_Ah + (size_t)sigma * HW;
        Pl = g_Al + (size_t)sigma * HW;
        Qh = g_XTh; Ql = g_XTl;
    } else {
        m0 = blk * 128;               // img*1024 + y
        n0 = blockIdx.y * 256;        // x
        Ph = g_Yh + (size_t)sigma * (NIMG * HW);
        Pl = g_Yl + (size_t)sigma * (NIMG * HW);
        Qh = g_Ah + (size_t)sigma * HW;
        Ql = g_Al + (size_t)sigma * HW;
    }
    int c0   = (PASS == 1) ? m0 : n0;
    int cext = (PASS == 1) ? 128 : 256;
    int kmin = max(0, c0 - p) & ~31;
    int kmax = min(1024, (c0 + cext + p + 31) & ~31);
    int nslab = (kmax - kmin) >> 5;

    float d[16][4];
#pragma unroll
    for (int i = 0; i < 16; ++i)
#pragma unroll
        for (int j = 0; j < 4; ++j) d[i][j] = 0.f;

    // ldmatrix per-lane base offsets (rows x 80B, 16B granules)
    u32 aoff = (u32)(((l & 7) + ((l >> 3) & 1) * 8) * 80 + (l >> 4) * 16);
    u32 boff = (u32)(((l & 7) + ((l >> 4) & 1) * 8) * 80 + ((l >> 3) & 1) * 16);

    // pipeline warmup
    stage_slab<PASS>(sb, Ph, Pl, Qh, Ql, m0, n0, kmin, tid);
    CP_COMMIT();
    int prefetched = 1;
    if (nslab > 1) {
        stage_slab<PASS>(sb + BUF, Ph, Pl, Qh, Ql, m0, n0, kmin + 32, tid);
        CP_COMMIT();
        prefetched = 2;
    }

    for (int i = 0; i < nslab; ++i) {
        if (prefetched - i - 1 > 0) CP_WAIT1(); else CP_WAIT0();
        __syncthreads();
        u32 sbuf = sb + (u32)(i & 1) * BUF;
        u32 aPh = sbuf + SPH + wm * (64 * 80) + aoff;
        u32 aPl = sbuf + SPL + wm * (64 * 80) + aoff;
        u32 bQh = sbuf + SQH + wn * (32 * 80) + boff;
        u32 bQl = sbuf + SQL + wn * (32 * 80) + boff;
#pragma unroll
        for (int kb = 0; kb < 2; ++kb) {
            u32 a[4][4], b1[2][4], b2[2][4];
#pragma unroll
            for (int mi = 0; mi < 4; ++mi) LDSM4(a[mi], aPh + mi * (16 * 80) + kb * 32);
#pragma unroll
            for (int nj = 0; nj < 2; ++nj) LDSM4(b1[nj], bQh + nj * (16 * 80) + kb * 32);
#pragma unroll
            for (int mi = 0; mi < 4; ++mi)
#pragma unroll
                for (int ni = 0; ni < 4; ++ni)
                    MMA16816(d[mi * 4 + ni], a[mi], b1[ni >> 1][(ni & 1) * 2], b1[ni >> 1][(ni & 1) * 2 + 1]);
#pragma unroll
            for (int nj = 0; nj < 2; ++nj) LDSM4(b2[nj], bQl + nj * (16 * 80) + kb * 32);
#pragma unroll
            for (int mi = 0; mi < 4; ++mi)
#pragma unroll
                for (int ni = 0; ni < 4; ++ni)
                    MMA16816(d[mi * 4 + ni], a[mi], b2[ni >> 1][(ni & 1) * 2], b2[ni >> 1][(ni & 1) * 2 + 1]);
#pragma unroll
            for (int mi = 0; mi < 4; ++mi) LDSM4(a[mi], aPl + mi * (16 * 80) + kb * 32);
#pragma unroll
            for (int mi = 0; mi < 4; ++mi)
#pragma unroll
                for (int ni = 0; ni < 4; ++ni)
                    MMA16816(d[mi * 4 + ni], a[mi], b1[ni >> 1][(ni & 1) * 2], b1[ni >> 1][(ni & 1) * 2 + 1]);
        }
        __syncthreads();
        if (prefetched < nslab) {
            stage_slab<PASS>(sb + (u32)(prefetched & 1) * BUF, Ph, Pl, Qh, Ql,
                             m0, n0, kmin + prefetched * 32, tid);
            CP_COMMIT();
            ++prefetched;
        }
    }

    // epilogue: d-frag map: rows t/4 (+8), cols (t%4)*2 (+1)
#pragma unroll
    for (int mi = 0; mi < 4; ++mi) {
#pragma unroll
        for (int ni = 0; ni < 4; ++ni) {
            float* dd = d[mi * 4 + ni];
            int gm0 = m0 + wm * 64 + mi * 16 + (l >> 2);
            int gc  = n0 + wn * 32 + ni * 8 + (l & 3) * 2;
#pragma unroll
            for (int h = 0; h < 2; ++h) {
                int gm = gm0 + h * 8;
                float v0 = dd[h * 2 + 0], v1 = dd[h * 2 + 1];
                if (PASS == 1) {
                    // out: Y[sigma][img = gc>>10][y = gm][x = gc&1023]
                    size_t o = (size_t)sigma * (NIMG * HW)
                             + ((size_t)(gc >> 10)) * HW + (size_t)gm * 1024 + (gc & 1023);
                    u16 h0, l0, h1, l1;
                    bf_split(v0, h0, l0);
                    bf_split(v1, h1, l1);
                    *(u32*)&g_Yh[o] = (u32)h0 | ((u32)h1 << 16);
                    *(u32*)&g_Yl[o] = (u32)l0 | ((u32)l1 << 16);
                } else {
                    // out: accS[sigma][gm = img*1024+y][gc = x]
                    size_t o = (size_t)sigma * (NIMG * HW) + (size_t)gm * 1024 + gc;
                    g_accS[o]     = logf(fmaxf(v0, EPSF));
                    g_accS[o + 1] = logf(fmaxf(v1, EPSF));
                }
            }
        }
    }
}

// ---------------------------------------------------------------------------
__global__ void fields_k(const float* __restrict__ inp, float* __restrict__ dout) {
    int total = NIMG * HW;
    for (int idx = blockIdx.x * blockDim.x + threadIdx.x; idx < total;
         idx += gridDim.x * blockDim.x) {
        float a = g_accS[idx] + g_accS[total + idx] + g_accS[2 * total + idx];
        float ib = a * (1.0f / 3.0f);
        float v  = inp[idx];
        float li = logf(fminf(fmaxf(v, EPSF), 1.0f));
        float refl  = li - ib;
        float illum = logf(fmaxf(v, EPSF)) - refl;
        dout[3 + idx]         = refl;
        dout[3 + total + idx] = illum;
    }
}

__global__ void grad_k(const float* __restrict__ dout) {
    const float* __restrict__ refl = dout + 3;
    const float* __restrict__ ill  = dout + 3 + NIMG * HW;
    float s0 = 0.f, s1 = 0.f, s2 = 0.f, s3 = 0.f;
    int total = NIMG * HW;
    for (int idx = blockIdx.x * blockDim.x + threadIdx.x; idx < total;
         idx += gridDim.x * blockDim.x) {
        int x = idx & 1023, y = (idx >> 10) & 1023;
        float r0 = refl[idx], i0 = ill[idx];
        if (x < 1023) { s0 += fabsf(r0 - refl[idx + 1]);    s2 += fabsf(i0 - ill[idx + 1]); }
        if (y < 1023) { s1 += fabsf(r0 - refl[idx + 1024]); s3 += fabsf(i0 - ill[idx + 1024]); }
    }
#pragma unroll
    for (int o = 16; o > 0; o >>= 1) {
        s0 += __shfl_down_sync(0xffffffffu, s0, o);
        s1 += __shfl_down_sync(0xffffffffu, s1, o);
        s2 += __shfl_down_sync(0xffffffffu, s2, o);
        s3 += __shfl_down_sync(0xffffffffu, s3, o);
    }
    __shared__ float sb[4][8];
    int wid = threadIdx.x >> 5, lid = threadIdx.x & 31;
    if (lid == 0) { sb[0][wid] = s0; sb[1][wid] = s1; sb[2][wid] = s2; sb[3][wid] = s3; }
    __syncthreads();
    if (threadIdx.x == 0) {
        float t0 = 0.f, t1 = 0.f, t2 = 0.f, t3 = 0.f;
        int nw = blockDim.x >> 5;
        for (int w = 0; w < nw; ++w) { t0 += sb[0][w]; t1 += sb[1][w]; t2 += sb[2][w]; t3 += sb[3][w]; }
        atomicAdd(&g_red[0], t0); atomicAdd(&g_red[1], t1);
        atomicAdd(&g_red[2], t2); atomicAdd(&g_red[3], t3);
    }
}

__global__ void fin_k(float* dout) {
    if (threadIdx.x == 0) {
        float ngx = (float)(NIMG * 1024 * 1023);
        float ngy = (float)(NIMG * 1023 * 1024);
        float ld = g_red[0] / ngx + g_red[1] / ngy;
        float ls = g_red[2] / ngx + g_red[3] / ngy;
        dout[0] = ls; dout[1] = ld; dout[2] = ls;   // DETAIL_W=0, ILLUM_W=1
    }
}

extern "C" void kernel_launch(void* const* d_in, const int* in_sizes, int n_in,
                              void* d_out, int out_size) {
    const float* inp = (const float*)d_in[0];
    float* out = (float*)d_out;

    cudaFuncSetAttribute(mma_k<1>, cudaFuncAttributeMaxDynamicSharedMemorySize, SMEM_MMA);
    cudaFuncSetAttribute(mma_k<2>, cudaFuncAttributeMaxDynamicSharedMemorySize, SMEM_MMA);

    init_kernels_k<<<1, 1024>>>();
    buildA_k<<<dim3(1024, 3), 256>>>();
    splitX_k<<<dim3(32, 32, NIMG), dim3(32, 32)>>>(inp);

    // all sigmas fused per pass; sigma = blockIdx.x % 3 (interleaved load balance)
    mma_k<1><<<dim3(8 * 3, 24), 512, SMEM_MMA>>>();   // Y[s] = A_s * X     (576 blocks)
    mma_k<2><<<dim3(48 * 3, 4), 512, SMEM_MMA>>>();   // accS[s] = log(Y_s * A_s^T)

    fields_k<<<4096, 256>>>(inp, out);
    grad_k<<<2048, 256>>>(out);
    fin_k<<<1, 32>>>(out);
}

// round 13
// speedup vs baseline: 3.1509x; 1.2094x over previous
#include <cuda_runtime.h>
#include <cuda_bf16.h>
#include <cstdint>
#include <math.h>

#define HH 1024
#define NIMG 6
#define HW (HH*HH)
#define EPSF 1e-3f

typedef unsigned short u16;
typedef unsigned int u32;

// ---------------- device scratch (allocation-free rule) ---------------------
__device__ u16 g_Ah[3*HW];          // blur matrices, bf16 hi, [sigma][i][j]
__device__ u16 g_Al[3*HW];          // lo
__device__ u16 g_XTh[NIMG*HW];      // clipped input transposed [img][x][u], hi
__device__ u16 g_XTl[NIMG*HW];      // lo
__device__ u16 g_Yh[3*NIMG*HW];     // vertical blur [sigma][img][y][x], hi
__device__ u16 g_Yl[3*NIMG*HW];     // lo
__device__ float g_accS[3*NIMG*HW]; // log(blur_sigma) [sigma][img][y][x]
__device__ float g_kern[2304];      // 1D kernels at offsets 0,128,640
__device__ float g_red[4];

__constant__ int c_p[3] = {45, 240, 750};

__device__ __forceinline__ u32 smem_u32(const void* p) {
    u32 a;
    asm("{ .reg .u64 t; cvta.to.shared.u64 t, %1; cvt.u32.u64 %0, t; }" : "=r"(a) : "l"(p));
    return a;
}
#define LDSM4(r, addr) asm volatile( \
    "ldmatrix.sync.aligned.m8n8.x4.shared.b16 {%0,%1,%2,%3}, [%4];" \
    : "=r"((r)[0]),"=r"((r)[1]),"=r"((r)[2]),"=r"((r)[3]) : "r"(addr))
#define MMA16816(dd, aa, b0, b1) asm volatile( \
    "mma.sync.aligned.m16n8k16.row.col.f32.bf16.bf16.f32 " \
    "{%0,%1,%2,%3},{%4,%5,%6,%7},{%8,%9},{%0,%1,%2,%3};" \
    : "+f"((dd)[0]),"+f"((dd)[1]),"+f"((dd)[2]),"+f"((dd)[3]) \
    : "r"((aa)[0]),"r"((aa)[1]),"r"((aa)[2]),"r"((aa)[3]), "r"(b0), "r"(b1))
#define CP16(dst, src)  asm volatile("cp.async.cg.shared.global [%0], [%1], 16;" :: "r"(dst), "l"(src))
#define CP_COMMIT()     asm volatile("cp.async.commit_group;" ::: "memory")
#define CP_WAIT0()      asm volatile("cp.async.wait_group 0;" ::: "memory")
#define CP_WAIT1()      asm volatile("cp.async.wait_group 1;" ::: "memory")

__device__ __forceinline__ void bf_split(float v, u16& h, u16& l) {
    __nv_bfloat16 bh = __float2bfloat16(v);
    h = __bfloat16_as_ushort(bh);
    l = __bfloat16_as_ushort(__float2bfloat16(v - __bfloat162float(bh)));
}

// ---------------------------------------------------------------------------
__global__ void init_kernels_k() {
    __shared__ float red[1024];
    const float sig[3] = {15.f, 80.f, 250.f};
    const int   ks [3] = {91, 481, 1501};
    const int   off[3] = {0, 128, 640};
    int tid = threadIdx.x;
    if (tid < 4) g_red[tid] = 0.f;
    for (int s = 0; s < 3; ++s) {
        int n = ks[s];
        float c = 0.5f * (float)(n - 1), inv = 1.0f / sig[s], local = 0.f;
        for (int t = tid; t < n; t += 1024) {
            float x = ((float)t - c) * inv;
            float v = expf(-0.5f * x * x);
            g_kern[off[s] + t] = v;
            local += v;
        }
        red[tid] = local;
        __syncthreads();
        for (int st = 512; st > 0; st >>= 1) {
            if (tid < st) red[tid] += red[tid + st];
            __syncthreads();
        }
        float s_inv = 1.0f / red[0];
        __syncthreads();
        for (int t = tid; t < n; t += 1024) g_kern[off[s] + t] *= s_inv;
    }
}

// ---------------------------------------------------------------------------
// Exact reflect-pad blur matrix, split bf16 hi/lo.
// A[i][j] = kt(j-i+p) + [j>0] kt(-j-i+p) + [j<1023] kt(2046-j-i+p)
// ---------------------------------------------------------------------------
__global__ void buildA_k() {
    const int ks [3] = {91, 481, 1501};
    const int off[3] = {0, 128, 640};
    const int pp [3] = {45, 240, 750};
    int i = blockIdx.x, s = blockIdx.y;
    int koff = off[s], kn = ks[s], p = pp[s];
    size_t base = (size_t)s * HW + (size_t)i * 1024;
    for (int j = threadIdx.x; j < 1024; j += blockDim.x) {
        float v = 0.f;
        int t0 = j - i + p;
        if (t0 >= 0 && t0 < kn) v += g_kern[koff + t0];
        int t1 = -j - i + p;
        if (j > 0 && t1 >= 0 && t1 < kn) v += g_kern[koff + t1];
        int t2 = 2046 - j - i + p;
        if (j < 1023 && t2 >= 0 && t2 < kn) v += g_kern[koff + t2];
        u16 h, l;
        bf_split(v, h, l);
        g_Ah[base + j] = h;
        g_Al[base + j] = l;
    }
}

__global__ void splitX_k(const float* __restrict__ inp) {
    __shared__ float sm[32][33];
    int x0 = blockIdx.x * 32, y0 = blockIdx.y * 32, img = blockIdx.z;
    int tx = threadIdx.x, ty = threadIdx.y;
    float v = inp[(size_t)img * HW + (size_t)(y0 + ty) * 1024 + x0 + tx];
    sm[ty][tx] = fminf(fmaxf(v, EPSF), 1.0f);
    __syncthreads();
    float w = sm[tx][ty];
    u16 h, l;
    bf_split(w, h, l);
    size_t o = (size_t)img * HW + (size_t)(x0 + ty) * 1024 + y0 + tx;
    g_XTh[o] = h;
    g_XTl[o] = l;
}

// ---------------------------------------------------------------------------
// Banded bf16x3 GEMM on mma.sync (base-ISA HMMA), 3-buffer cp.async pipeline
// staged 2 slabs ahead, ONE barrier per K-slab.
//   At iter i: read slot i%3; stage slab i+2 into slot (i+2)%3, which was last
//   read at iter i-1 — ordered by the top-of-iter-i barrier. (R11 staged i+3
//   into i%3: a write race on the live buffer. Fixed.)
// D[M x N] = P(M x K).Q(N x K)^T, K in gaussian band.
// 512 thr = 16 warps, warp tile m64 x n32.
//   PASS1: tile 128x256, warps 2x8. P=A_s rows y (band driver), Q=XT.
//   PASS2: tile 256x128, warps 4x4. P=Y_s, Q=A_s rows x (band driver = N ext).
// smem rows padded to 80B (ldmatrix conflict-free); 3 x 60KB buffers.
// ---------------------------------------------------------------------------
#define BUF 61440
#define SMEM_MMA (3*BUF)

template<int TM, int TN>
__device__ __forceinline__ void stage_slab(u32 sa, const u16* Ph, const u16* Pl,
                                           const u16* Qh, const u16* Ql,
                                           int m0, int n0, int k0, int tid) {
    const int OPL = TM * 80, OQH = 2 * TM * 80, OQL = 2 * TM * 80 + TN * 80;
#pragma unroll
    for (int q = 0; q < TM / 128; ++q) {
        int it = tid + q * 512, prow = it >> 2, pg = it & 3;
        size_t src = ((size_t)(m0 + prow) * 1024 + k0) * 2 + pg * 16;
        CP16(sa + prow * 80 + pg * 16, (const char*)Ph + src);
        CP16(sa + OPL + prow * 80 + pg * 16, (const char*)Pl + src);
    }
#pragma unroll
    for (int q = 0; q < TN / 128; ++q) {
        int it = tid + q * 512, qrow = it >> 2, qg = it & 3;
        size_t src = ((size_t)(n0 + qrow) * 1024 + k0) * 2 + qg * 16;
        CP16(sa + OQH + qrow * 80 + qg * 16, (const char*)Qh + src);
        CP16(sa + OQL + qrow * 80 + qg * 16, (const char*)Ql + src);
    }
}

template<int PASS>
__global__ void __launch_bounds__(512, 1) mma_k() {
    constexpr int TM = (PASS == 1) ? 128 : 256;
    constexpr int TN = (PASS == 1) ? 256 : 128;
    constexpr int WN = TN / 32;                 // n-warps (8 or 4)
    const int OPL = TM * 80, OQH = 2 * TM * 80, OQL = 2 * TM * 80 + TN * 80;

    extern __shared__ char sm[];
    u32 sb = smem_u32(sm);
    int tid = threadIdx.x, wid = tid >> 5, l = tid & 31;
    int wm = wid / WN, wn = wid % WN;

    int sigma = blockIdx.x % 3;
    int blk   = blockIdx.x / 3;
    int p = c_p[sigma];
    int m0 = blk * TM, n0 = blockIdx.y * TN;
    const u16 *Ph, *Pl, *Qh, *Ql;
    if (PASS == 1) {
        Ph = g_Ah + (size_t)sigma * HW;  Pl = g_Al + (size_t)sigma * HW;
        Qh = g_XTh;                      Ql = g_XTl;
    } else {
        Ph = g_Yh + (size_t)sigma * (NIMG * HW);
        Pl = g_Yl + (size_t)sigma * (NIMG * HW);
        Qh = g_Ah + (size_t)sigma * HW;  Ql = g_Al + (size_t)sigma * HW;
    }
    int c0   = (PASS == 1) ? m0 : n0;
    int kmin = max(0, c0 - p) & ~31;
    int kmax = min(1024, (c0 + ((PASS == 1) ? TM : TN) + p + 31) & ~31);
    int nslab = (kmax - kmin) >> 5;

    float d[16][4];
#pragma unroll
    for (int i = 0; i < 16; ++i)
#pragma unroll
        for (int j = 0; j < 4; ++j) d[i][j] = 0.f;

    u32 aoff = (u32)(((l & 7) + ((l >> 3) & 1) * 8) * 80 + (l >> 4) * 16);
    u32 boff = (u32)(((l & 7) + ((l >> 4) & 1) * 8) * 80 + ((l >> 3) & 1) * 16);

    // warmup: prefetch 2 slabs (slots 0, 1)
    int prefetched = 0;
#pragma unroll
    for (int w = 0; w < 2; ++w) {
        if (w < nslab) {
            stage_slab<TM, TN>(sb + w * BUF, Ph, Pl, Qh, Ql, m0, n0, kmin + w * 32, tid);
            CP_COMMIT();
            ++prefetched;
        }
    }

    for (int i = 0; i < nslab; ++i) {
        if (prefetched - i - 1 > 0) CP_WAIT1(); else CP_WAIT0();
        __syncthreads();                      // single barrier per slab
        u32 sbuf = sb + (u32)(i % 3) * BUF;
        u32 aPh = sbuf + wm * (64 * 80) + aoff;
        u32 aPl = sbuf + OPL + wm * (64 * 80) + aoff;
        u32 bQh = sbuf + OQH + wn * (32 * 80) + boff;
        u32 bQl = sbuf + OQL + wn * (32 * 80) + boff;
#pragma unroll
        for (int kb = 0; kb < 2; ++kb) {
            u32 a[4][4], a2[4][4], b1[2][4], b2[2][4];
#pragma unroll
            for (int mi = 0; mi < 4; ++mi) LDSM4(a[mi], aPh + mi * (16 * 80) + kb * 32);
#pragma unroll
            for (int nj = 0; nj < 2; ++nj) LDSM4(b1[nj], bQh + nj * (16 * 80) + kb * 32);
#pragma unroll
            for (int nj = 0; nj < 2; ++nj) LDSM4(b2[nj], bQl + nj * (16 * 80) + kb * 32);
            // g1: Phi x Qhi
#pragma unroll
            for (int mi = 0; mi < 4; ++mi)
#pragma unroll
                for (int ni = 0; ni < 4; ++ni)
                    MMA16816(d[mi * 4 + ni], a[mi], b1[ni >> 1][(ni & 1) * 2], b1[ni >> 1][(ni & 1) * 2 + 1]);
#pragma unroll
            for (int mi = 0; mi < 4; ++mi) LDSM4(a2[mi], aPl + mi * (16 * 80) + kb * 32);
            // g2: Phi x Qlo
#pragma unroll
            for (int mi = 0; mi < 4; ++mi)
#pragma unroll
                for (int ni = 0; ni < 4; ++ni)
                    MMA16816(d[mi * 4 + ni], a[mi], b2[ni >> 1][(ni & 1) * 2], b2[ni >> 1][(ni & 1) * 2 + 1]);
            // g3: Plo x Qhi
#pragma unroll
            for (int mi = 0; mi < 4; ++mi)
#pragma unroll
                for (int ni = 0; ni < 4; ++ni)
                    MMA16816(d[mi * 4 + ni], a2[mi], b1[ni >> 1][(ni & 1) * 2], b1[ni >> 1][(ni & 1) * 2 + 1]);
        }
        // stage slab i+2 into slot (i+2)%3 — last read at iter i-1, safe.
        if (prefetched < nslab) {
            stage_slab<TM, TN>(sb + (u32)(prefetched % 3) * BUF, Ph, Pl, Qh, Ql,
                               m0, n0, kmin + prefetched * 32, tid);
            CP_COMMIT();
            ++prefetched;
        }
    }

    // epilogue: d-frag map: rows t/4 (+8), cols (t%4)*2 (+1)
#pragma unroll
    for (int mi = 0; mi < 4; ++mi) {
#pragma unroll
        for (int ni = 0; ni < 4; ++ni) {
            float* dd = d[mi * 4 + ni];
            int gm0 = m0 + wm * 64 + mi * 16 + (l >> 2);
            int gc  = n0 + wn * 32 + ni * 8 + (l & 3) * 2;
#pragma unroll
            for (int h = 0; h < 2; ++h) {
                int gm = gm0 + h * 8;
                float v0 = dd[h * 2 + 0], v1 = dd[h * 2 + 1];
                if (PASS == 1) {
                    // out: Y[sigma][img = gc>>10][y = gm][x = gc&1023]
                    size_t o = (size_t)sigma * (NIMG * HW)
                             + ((size_t)(gc >> 10)) * HW + (size_t)gm * 1024 + (gc & 1023);
                    u16 h0, l0, h1, l1;
                    bf_split(v0, h0, l0);
                    bf_split(v1, h1, l1);
                    *(u32*)&g_Yh[o] = (u32)h0 | ((u32)h1 << 16);
                    *(u32*)&g_Yl[o] = (u32)l0 | ((u32)l1 << 16);
                } else {
                    // out: accS[sigma][gm = img*1024+y][gc = x]
                    size_t o = (size_t)sigma * (NIMG * HW) + (size_t)gm * 1024 + gc;
                    g_accS[o]     = logf(fmaxf(v0, EPSF));
                    g_accS[o + 1] = logf(fmaxf(v1, EPSF));
                }
            }
        }
    }
}

// ---------------------------------------------------------------------------
__global__ void fields_k(const float* __restrict__ inp, float* __restrict__ dout) {
    int total = NIMG * HW;
    for (int idx = blockIdx.x * blockDim.x + threadIdx.x; idx < total;
         idx += gridDim.x * blockDim.x) {
        float a = g_accS[idx] + g_accS[total + idx] + g_accS[2 * total + idx];
        float ib = a * (1.0f / 3.0f);
        float v  = inp[idx];
        float li = logf(fminf(fmaxf(v, EPSF), 1.0f));
        float refl  = li - ib;
        float illum = logf(fmaxf(v, EPSF)) - refl;
        dout[3 + idx]         = refl;
        dout[3 + total + idx] = illum;
    }
}

__global__ void grad_k(const float* __restrict__ dout) {
    const float* __restrict__ refl = dout + 3;
    const float* __restrict__ ill  = dout + 3 + NIMG * HW;
    float s0 = 0.f, s1 = 0.f, s2 = 0.f, s3 = 0.f;
    int total = NIMG * HW;
    for (int idx = blockIdx.x * blockDim.x + threadIdx.x; idx < total;
         idx += gridDim.x * blockDim.x) {
        int x = idx & 1023, y = (idx >> 10) & 1023;
        float r0 = refl[idx], i0 = ill[idx];
        if (x < 1023) { s0 += fabsf(r0 - refl[idx + 1]);    s2 += fabsf(i0 - ill[idx + 1]); }
        if (y < 1023) { s1 += fabsf(r0 - refl[idx + 1024]); s3 += fabsf(i0 - ill[idx + 1024]); }
    }
#pragma unroll
    for (int o = 16; o > 0; o >>= 1) {
        s0 += __shfl_down_sync(0xffffffffu, s0, o);
        s1 += __shfl_down_sync(0xffffffffu, s1, o);
        s2 += __shfl_down_sync(0xffffffffu, s2, o);
        s3 += __shfl_down_sync(0xffffffffu, s3, o);
    }
    __shared__ float sb[4][8];
    int wid = threadIdx.x >> 5, lid = threadIdx.x & 31;
    if (lid == 0) { sb[0][wid] = s0; sb[1][wid] = s1; sb[2][wid] = s2; sb[3][wid] = s3; }
    __syncthreads();
    if (threadIdx.x == 0) {
        float t0 = 0.f, t1 = 0.f, t2 = 0.f, t3 = 0.f;
        int nw = blockDim.x >> 5;
        for (int w = 0; w < nw; ++w) { t0 += sb[0][w]; t1 += sb[1][w]; t2 += sb[2][w]; t3 += sb[3][w]; }
        atomicAdd(&g_red[0], t0); atomicAdd(&g_red[1], t1);
        atomicAdd(&g_red[2], t2); atomicAdd(&g_red[3], t3);
    }
}

__global__ void fin_k(float* dout) {
    if (threadIdx.x == 0) {
        float ngx = (float)(NIMG * 1024 * 1023);
        float ngy = (float)(NIMG * 1023 * 1024);
        float ld = g_red[0] / ngx + g_red[1] / ngy;
        float ls = g_red[2] / ngx + g_red[3] / ngy;
        dout[0] = ls; dout[1] = ld; dout[2] = ls;   // DETAIL_W=0, ILLUM_W=1
    }
}

extern "C" void kernel_launch(void* const* d_in, const int* in_sizes, int n_in,
                              void* d_out, int out_size) {
    const float* inp = (const float*)d_in[0];
    float* out = (float*)d_out;

    cudaFuncSetAttribute(mma_k<1>, cudaFuncAttributeMaxDynamicSharedMemorySize, SMEM_MMA);
    cudaFuncSetAttribute(mma_k<2>, cudaFuncAttributeMaxDynamicSharedMemorySize, SMEM_MMA);

    init_kernels_k<<<1, 1024>>>();
    buildA_k<<<dim3(1024, 3), 256>>>();
    splitX_k<<<dim3(32, 32, NIMG), dim3(32, 32)>>>(inp);

    // sigma = blockIdx.x % 3 (interleaved load balance), all sigmas per launch
    mma_k<1><<<dim3(8 * 3, 24), 512, SMEM_MMA>>>();   // Y[s] = A_s * X   (tile 128x256)
    mma_k<2><<<dim3(24 * 3, 8), 512, SMEM_MMA>>>();   // accS[s] = log(Y_s * A_s^T) (256x128)

    fields_k<<<4096, 256>>>(inp, out);
    grad_k<<<2048, 256>>>(out);
    fin_k<<<1, 32>>>(out);
}